// round 6
// baseline (speedup 1.0000x reference)
#include <cuda_runtime.h>
#include <cuda_fp16.h>
#include <cstdint>

// ============================================================================
// out[8192,4096] = x[8192,4096] @ W[4096(k),4096(n)] + b
// sm_103 base-ISA: cp.async 4-stage + ldmatrix + mma.sync.m16n8k16 (fp32 acc)
// R6: 512 threads / 16 warps (2M x 8N, warp tile 64x32) for 4 warps/SMSP.
//     Cross-iteration kk=0 prefetch kept from R5. Target: tensor 78 -> ~86%.
// ============================================================================

static constexpr int BATCH = 8192;
static constexpr int IN_F  = 4096;   // K
static constexpr int OUT_F = 4096;   // N

static constexpr int TM = 128;
static constexpr int TN = 256;
static constexpr int KS = 64;              // K per stage (128B rows)
static constexpr int NK = IN_F / KS;       // 64
static constexpr int STAGES = 4;

static constexpr uint32_t A_ST = TM * 128u;                 // 16 KB
static constexpr uint32_t B_ST = TN * 128u;                 // 32 KB
static constexpr uint32_t STAGE = A_ST + B_ST;              // 48 KB
static constexpr uint32_t SMEM_BYTES = 1024u + STAGES * STAGE;

__device__ __align__(128) __half g_xh[(size_t)BATCH * IN_F];  // x fp16 [M,K]
__device__ __align__(128) __half g_wt[(size_t)OUT_F * IN_F];  // W^T fp16 [N,K]

// ----------------------------------------------------------------------------
__device__ __forceinline__ uint32_t smem_u32(const void* p) {
    uint32_t a;
    asm("{ .reg .u64 t; cvta.to.shared.u64 t, %1; cvt.u32.u64 %0, t; }" : "=r"(a) : "l"(p));
    return a;
}
__device__ __forceinline__ uint32_t sw128(uint32_t off) {
    return off ^ ((off >> 3) & 0x70u);
}
__device__ __forceinline__ void cp16(uint32_t s, const void* g) {
    asm volatile("cp.async.cg.shared.global [%0], [%1], 16;" :: "r"(s), "l"(g));
}
__device__ __forceinline__ void ldsm4(uint32_t& r0, uint32_t& r1, uint32_t& r2, uint32_t& r3,
                                      uint32_t addr) {
    asm volatile("ldmatrix.sync.aligned.m8n8.x4.shared.b16 {%0,%1,%2,%3}, [%4];"
                 : "=r"(r0), "=r"(r1), "=r"(r2), "=r"(r3) : "r"(addr));
}
__device__ __forceinline__ void mma16816(float& c0, float& c1, float& c2, float& c3,
                                         uint32_t a0, uint32_t a1, uint32_t a2, uint32_t a3,
                                         uint32_t b0, uint32_t b1) {
    asm volatile(
        "mma.sync.aligned.m16n8k16.row.col.f32.f16.f16.f32 "
        "{%0,%1,%2,%3}, {%4,%5,%6,%7}, {%8,%9}, {%0,%1,%2,%3};"
        : "+f"(c0), "+f"(c1), "+f"(c2), "+f"(c3)
        : "r"(a0), "r"(a1), "r"(a2), "r"(a3), "r"(b0), "r"(b1));
}

// ----------------------------------------------------------------------------
// Fused preprocessing: blocks [0, W_BLOCKS) transpose+convert W; rest convert x.
// ----------------------------------------------------------------------------
static constexpr int W_BLOCKS = (OUT_F / 32) * (IN_F / 32);   // 16384
static constexpr int X_BLOCKS = 4096;

__global__ void __launch_bounds__(256)
cvt_fused_kernel(const float* __restrict__ x, const float* __restrict__ w) {
    const int bid = blockIdx.x;
    if (bid < W_BLOCKS) {
        __shared__ __half tile[32][33];
        const int bx = bid & ((OUT_F / 32) - 1);
        const int by = bid >> 7;
        const int i0 = by * 32;
        const int o0 = bx * 32;
        const int tx = threadIdx.x & 31;
        const int ty = threadIdx.x >> 5;
        #pragma unroll
        for (int k = 0; k < 4; k++) {
            int i = i0 + ty + k * 8;
            tile[ty + k * 8][tx] = __float2half(w[(size_t)i * OUT_F + o0 + tx]);
        }
        __syncthreads();
        #pragma unroll
        for (int k = 0; k < 4; k++) {
            int o = o0 + ty + k * 8;
            g_wt[(size_t)o * IN_F + i0 + tx] = tile[tx][ty + k * 8];
        }
    } else {
        const size_t n8 = (size_t)BATCH * IN_F / 8;
        const size_t stride = (size_t)X_BLOCKS * 256;
        for (size_t i = (size_t)(bid - W_BLOCKS) * 256 + threadIdx.x; i < n8; i += stride) {
            float4 a = ((const float4*)x)[2 * i];
            float4 c = ((const float4*)x)[2 * i + 1];
            __half2 h0 = __floats2half2_rn(a.x, a.y);
            __half2 h1 = __floats2half2_rn(a.z, a.w);
            __half2 h2 = __floats2half2_rn(c.x, c.y);
            __half2 h3 = __floats2half2_rn(c.z, c.w);
            uint4 o;
            o.x = *reinterpret_cast<uint32_t*>(&h0);
            o.y = *reinterpret_cast<uint32_t*>(&h1);
            o.z = *reinterpret_cast<uint32_t*>(&h2);
            o.w = *reinterpret_cast<uint32_t*>(&h3);
            ((uint4*)g_xh)[i] = o;
        }
    }
}

// ----------------------------------------------------------------------------
// GEMM: 128x256 tile / CTA, 512 threads (16 warps: 2M x 8N, warp tile 64x32)
// ----------------------------------------------------------------------------
__device__ __forceinline__ void load_chunk(uint32_t st, int tid,
                                           const __half* a, const __half* b, int q) {
    if (q < 2) {
        int id = tid + (q << 9);            // A: 1024 chunks / 512 thr
        int row = id >> 3;
        int c = id & 7;
        uint32_t sw = sw128(((uint32_t)row << 7) | ((uint32_t)c << 4));
        cp16(st + sw, a + (size_t)row * IN_F + (c << 3));
    } else {
        int id = tid + ((q - 2) << 9);      // B: 2048 chunks / 512 thr
        int row = id >> 3;
        int c = id & 7;
        uint32_t sw = sw128(((uint32_t)row << 7) | ((uint32_t)c << 4));
        cp16(st + A_ST + sw, b + (size_t)row * IN_F + (c << 3));
    }
}

__device__ __forceinline__ void load_stage(uint32_t st, int tid,
                                           const __half* gA, const __half* gB, int kslab) {
    const __half* a = gA + (size_t)kslab * KS;
    const __half* b = gB + (size_t)kslab * KS;
    #pragma unroll
    for (int q = 0; q < 6; q++) load_chunk(st, tid, a, b, q);
}

__global__ void __launch_bounds__(512, 1)
gemm_hmma_kernel(const float* __restrict__ bias, float* __restrict__ out) {
    extern __shared__ char smem_raw[];
    const uint32_t S0 = (smem_u32(smem_raw) + 1023u) & ~1023u;

    const int tid  = threadIdx.x;
    const int wid  = tid >> 5;
    const int lane = tid & 31;
    const int wm   = wid & 1;          // 0..1  (64 M-rows each)
    const int wn   = wid >> 1;         // 0..7  (32 N-cols each)
    const int tile_m = blockIdx.x >> 4;
    const int tile_n = blockIdx.x & 15;

    const __half* gA = g_xh + (size_t)tile_m * TM * IN_F;
    const __half* gB = g_wt + (size_t)tile_n * TN * IN_F;

    const uint32_t a_row  = (uint32_t)(wm * 64 + (lane & 15));
    const uint32_t a_colb = (uint32_t)((lane >> 4) << 4);
    const uint32_t b_row  = (uint32_t)(wn * 32 + ((lane >> 4) << 3) + (lane & 7));
    const uint32_t b_colb = (uint32_t)(((lane >> 3) & 1) << 4);

    float acc[4][4][4];
    #pragma unroll
    for (int t = 0; t < 4; t++)
        #pragma unroll
        for (int j = 0; j < 4; j++)
            #pragma unroll
            for (int q = 0; q < 4; q++) acc[t][j][q] = 0.0f;

    // Prologue: fill stages 0..2
    #pragma unroll
    for (int p = 0; p < STAGES - 1; p++) {
        load_stage(S0 + (uint32_t)p * STAGE, tid, gA, gB, p);
        asm volatile("cp.async.commit_group;" ::: "memory");
    }
    asm volatile("cp.async.wait_group 1;" ::: "memory");   // stages 0,1 complete
    __syncthreads();

    uint32_t af[2][4][4];   // A: 4 ldsm.x4 per buffer
    uint32_t bf[2][2][4];   // B: 2 ldsm.x4 per buffer (32 cols)

    // Preload iteration 0 / kk=0 fragments into buffer 0
    #pragma unroll
    for (int t = 0; t < 4; t++) {
        uint32_t off = (a_row + t * 16u) * 128u + a_colb;
        ldsm4(af[0][t][0], af[0][t][1], af[0][t][2], af[0][t][3], S0 + sw128(off));
    }
    #pragma unroll
    for (int p = 0; p < 2; p++) {
        uint32_t off = (b_row + p * 16u) * 128u + b_colb;
        ldsm4(bf[0][p][0], bf[0][p][1], bf[0][p][2], bf[0][p][3], S0 + A_ST + sw128(off));
    }

    for (int it = 0; it < NK; ++it) {
        const uint32_t stA = S0 + (uint32_t)(it % STAGES) * STAGE;
        const uint32_t stB = stA + A_ST;
        const uint32_t stNext = S0 + (uint32_t)((it + 1) % STAGES) * STAGE;
        const bool last = (it == NK - 1);

        const int j = it + (STAGES - 1);
        const bool doload = (j < NK);
        const uint32_t stJ = S0 + (uint32_t)(j % STAGES) * STAGE;
        const __half* nA = gA + (size_t)j * KS;
        const __half* nB = gB + (size_t)j * KS;

        #pragma unroll
        for (int kk = 0; kk < 4; kk++) {
            const int cur = kk & 1;
            const int nxt = cur ^ 1;
            // prefetch fragments: kk+1 of this stage, or kk=0 of NEXT stage at kk=3
            if (kk < 3) {
                const uint32_t kc = (uint32_t)((kk + 1) * 32);
                #pragma unroll
                for (int t = 0; t < 4; t++) {
                    uint32_t off = (a_row + t * 16u) * 128u + kc + a_colb;
                    ldsm4(af[nxt][t][0], af[nxt][t][1], af[nxt][t][2], af[nxt][t][3],
                          stA + sw128(off));
                }
                #pragma unroll
                for (int p = 0; p < 2; p++) {
                    uint32_t off = (b_row + p * 16u) * 128u + kc + b_colb;
                    ldsm4(bf[nxt][p][0], bf[nxt][p][1], bf[nxt][p][2], bf[nxt][p][3],
                          stB + sw128(off));
                }
            } else if (!last) {
                #pragma unroll
                for (int t = 0; t < 4; t++) {
                    uint32_t off = (a_row + t * 16u) * 128u + a_colb;
                    ldsm4(af[nxt][t][0], af[nxt][t][1], af[nxt][t][2], af[nxt][t][3],
                          stNext + sw128(off));
                }
                #pragma unroll
                for (int p = 0; p < 2; p++) {
                    uint32_t off = (b_row + p * 16u) * 128u + b_colb;
                    ldsm4(bf[nxt][p][0], bf[nxt][p][1], bf[nxt][p][2], bf[nxt][p][3],
                          stNext + A_ST + sw128(off));
                }
            }
            // spread next-stage global loads: 6 chunks over kk=0..2 (2 per kk)
            if (doload && kk < 3) {
                load_chunk(stJ, tid, nA, nB, kk * 2);
                load_chunk(stJ, tid, nA, nB, kk * 2 + 1);
            }
            // 16 MMAs on current fragments (4 M-steps x 4 n8)
            #pragma unroll
            for (int t = 0; t < 4; t++) {
                #pragma unroll
                for (int p = 0; p < 2; p++) {
                    mma16816(acc[t][2*p][0], acc[t][2*p][1], acc[t][2*p][2], acc[t][2*p][3],
                             af[cur][t][0], af[cur][t][1], af[cur][t][2], af[cur][t][3],
                             bf[cur][p][0], bf[cur][p][1]);
                    mma16816(acc[t][2*p+1][0], acc[t][2*p+1][1], acc[t][2*p+1][2], acc[t][2*p+1][3],
                             af[cur][t][0], af[cur][t][1], af[cur][t][2], af[cur][t][3],
                             bf[cur][p][2], bf[cur][p][3]);
                }
            }
        }
        asm volatile("cp.async.commit_group;" ::: "memory");
        if (!last) {
            asm volatile("cp.async.wait_group 1;" ::: "memory");
            __syncthreads();
        }
    }

    // Epilogue: acc + bias -> gmem fp32
    const int n_base = tile_n * TN + wn * 32 + (lane & 3) * 2;
    float2 bv[4];
    #pragma unroll
    for (int jj = 0; jj < 4; jj++)
        bv[jj] = *(const float2*)(bias + n_base + jj * 8);

    const int m_base = tile_m * TM + wm * 64 + (lane >> 2);
    #pragma unroll
    for (int t = 0; t < 4; t++) {
        float* r0 = out + (size_t)(m_base + t * 16) * OUT_F + n_base;
        float* r1 = r0 + 8 * OUT_F;
        #pragma unroll
        for (int jj = 0; jj < 4; jj++) {
            float2 v0 = make_float2(acc[t][jj][0] + bv[jj].x, acc[t][jj][1] + bv[jj].y);
            float2 v1 = make_float2(acc[t][jj][2] + bv[jj].x, acc[t][jj][3] + bv[jj].y);
            *(float2*)(r0 + jj * 8) = v0;
            *(float2*)(r1 + jj * 8) = v1;
        }
    }
}

// ----------------------------------------------------------------------------
extern "C" void kernel_launch(void* const* d_in, const int* in_sizes, int n_in,
                              void* d_out, int out_size) {
    (void)in_sizes; (void)n_in; (void)out_size;
    const float* x = (const float*)d_in[0];
    const float* w = (const float*)d_in[1];
    const float* b = (const float*)d_in[2];
    float* out = (float*)d_out;

    cvt_fused_kernel<<<W_BLOCKS + X_BLOCKS, 256>>>(x, w);

    cudaFuncSetAttribute(gemm_hmma_kernel, cudaFuncAttributeMaxDynamicSharedMemorySize,
                         (int)SMEM_BYTES);
    gemm_hmma_kernel<<<(BATCH / TM) * (OUT_F / TN), 512, SMEM_BYTES>>>(b, out);
}

// round 7
// speedup vs baseline: 1.0702x; 1.0702x over previous
#include <cuda_runtime.h>
#include <cuda_fp16.h>
#include <cstdint>

// ============================================================================
// out[8192,4096] = x[8192,4096] @ W[4096(k),4096(n)] + b
// sm_103 base-ISA: cp.async 3-stage + ldmatrix + mma.sync.m16n8k16 (fp32 acc)
// R7: 2 CTAs/SM (128 thr, 128x128 tile, warp tile 64x64 kept for reuse).
//     Independent CTA barriers cover each other's sync/ldsm exposure.
// ============================================================================

static constexpr int BATCH = 8192;
static constexpr int IN_F  = 4096;   // K
static constexpr int OUT_F = 4096;   // N

static constexpr int TM = 128;
static constexpr int TN = 128;
static constexpr int KS = 64;              // K per stage (128B rows)
static constexpr int NK = IN_F / KS;       // 64
static constexpr int STAGES = 3;

static constexpr uint32_t A_ST = TM * 128u;                 // 16 KB
static constexpr uint32_t B_ST = TN * 128u;                 // 16 KB
static constexpr uint32_t STAGE = A_ST + B_ST;              // 32 KB
static constexpr uint32_t SMEM_BYTES = 1024u + STAGES * STAGE;  // ~99 KB

__device__ __align__(128) __half g_xh[(size_t)BATCH * IN_F];  // x fp16 [M,K]
__device__ __align__(128) __half g_wt[(size_t)OUT_F * IN_F];  // W^T fp16 [N,K]

// ----------------------------------------------------------------------------
__device__ __forceinline__ uint32_t smem_u32(const void* p) {
    uint32_t a;
    asm("{ .reg .u64 t; cvta.to.shared.u64 t, %1; cvt.u32.u64 %0, t; }" : "=r"(a) : "l"(p));
    return a;
}
__device__ __forceinline__ uint32_t sw128(uint32_t off) {
    return off ^ ((off >> 3) & 0x70u);
}
__device__ __forceinline__ void cp16(uint32_t s, const void* g) {
    asm volatile("cp.async.cg.shared.global [%0], [%1], 16;" :: "r"(s), "l"(g));
}
__device__ __forceinline__ void ldsm4(uint32_t& r0, uint32_t& r1, uint32_t& r2, uint32_t& r3,
                                      uint32_t addr) {
    asm volatile("ldmatrix.sync.aligned.m8n8.x4.shared.b16 {%0,%1,%2,%3}, [%4];"
                 : "=r"(r0), "=r"(r1), "=r"(r2), "=r"(r3) : "r"(addr));
}
__device__ __forceinline__ void mma16816(float& c0, float& c1, float& c2, float& c3,
                                         uint32_t a0, uint32_t a1, uint32_t a2, uint32_t a3,
                                         uint32_t b0, uint32_t b1) {
    asm volatile(
        "mma.sync.aligned.m16n8k16.row.col.f32.f16.f16.f32 "
        "{%0,%1,%2,%3}, {%4,%5,%6,%7}, {%8,%9}, {%0,%1,%2,%3};"
        : "+f"(c0), "+f"(c1), "+f"(c2), "+f"(c3)
        : "r"(a0), "r"(a1), "r"(a2), "r"(a3), "r"(b0), "r"(b1));
}

// ----------------------------------------------------------------------------
// Fused preprocessing: blocks [0, W_BLOCKS) transpose+convert W; rest convert x.
// ----------------------------------------------------------------------------
static constexpr int W_BLOCKS = (OUT_F / 32) * (IN_F / 32);   // 16384
static constexpr int X_BLOCKS = 4096;

__global__ void __launch_bounds__(256)
cvt_fused_kernel(const float* __restrict__ x, const float* __restrict__ w) {
    const int bid = blockIdx.x;
    if (bid < W_BLOCKS) {
        __shared__ __half tile[32][33];
        const int bx = bid & ((OUT_F / 32) - 1);
        const int by = bid >> 7;
        const int i0 = by * 32;
        const int o0 = bx * 32;
        const int tx = threadIdx.x & 31;
        const int ty = threadIdx.x >> 5;
        #pragma unroll
        for (int k = 0; k < 4; k++) {
            int i = i0 + ty + k * 8;
            tile[ty + k * 8][tx] = __float2half(w[(size_t)i * OUT_F + o0 + tx]);
        }
        __syncthreads();
        #pragma unroll
        for (int k = 0; k < 4; k++) {
            int o = o0 + ty + k * 8;
            g_wt[(size_t)o * IN_F + i0 + tx] = tile[tx][ty + k * 8];
        }
    } else {
        const size_t n8 = (size_t)BATCH * IN_F / 8;
        const size_t stride = (size_t)X_BLOCKS * 256;
        for (size_t i = (size_t)(bid - W_BLOCKS) * 256 + threadIdx.x; i < n8; i += stride) {
            float4 a = ((const float4*)x)[2 * i];
            float4 c = ((const float4*)x)[2 * i + 1];
            __half2 h0 = __floats2half2_rn(a.x, a.y);
            __half2 h1 = __floats2half2_rn(a.z, a.w);
            __half2 h2 = __floats2half2_rn(c.x, c.y);
            __half2 h3 = __floats2half2_rn(c.z, c.w);
            uint4 o;
            o.x = *reinterpret_cast<uint32_t*>(&h0);
            o.y = *reinterpret_cast<uint32_t*>(&h1);
            o.z = *reinterpret_cast<uint32_t*>(&h2);
            o.w = *reinterpret_cast<uint32_t*>(&h3);
            ((uint4*)g_xh)[i] = o;
        }
    }
}

// ----------------------------------------------------------------------------
// GEMM: 128x128 tile / CTA, 128 threads (4 warps: 2M x 2N, warp tile 64x64)
// ----------------------------------------------------------------------------
__device__ __forceinline__ void load_chunk(uint32_t st, int tid,
                                           const __half* a, const __half* b, int q) {
    if (q < 8) {
        int id = tid + (q << 7);            // A: 1024 chunks / 128 thr
        int row = id >> 3;
        int c = id & 7;
        uint32_t sw = sw128(((uint32_t)row << 7) | ((uint32_t)c << 4));
        cp16(st + sw, a + (size_t)row * IN_F + (c << 3));
    } else {
        int id = tid + ((q - 8) << 7);      // B: 1024 chunks / 128 thr
        int row = id >> 3;
        int c = id & 7;
        uint32_t sw = sw128(((uint32_t)row << 7) | ((uint32_t)c << 4));
        cp16(st + A_ST + sw, b + (size_t)row * IN_F + (c << 3));
    }
}

__device__ __forceinline__ void load_stage(uint32_t st, int tid,
                                           const __half* gA, const __half* gB, int kslab) {
    const __half* a = gA + (size_t)kslab * KS;
    const __half* b = gB + (size_t)kslab * KS;
    #pragma unroll
    for (int q = 0; q < 16; q++) load_chunk(st, tid, a, b, q);
}

__global__ void __launch_bounds__(128, 2)
gemm_hmma_kernel(const float* __restrict__ bias, float* __restrict__ out) {
    extern __shared__ char smem_raw[];
    const uint32_t S0 = (smem_u32(smem_raw) + 1023u) & ~1023u;

    const int tid  = threadIdx.x;
    const int wid  = tid >> 5;
    const int lane = tid & 31;
    const int wm   = wid & 1;          // 0..1  (64 M-rows each)
    const int wn   = wid >> 1;         // 0..1  (64 N-cols each)
    const int tile_m = blockIdx.x >> 5;    // 64 m-tiles
    const int tile_n = blockIdx.x & 31;    // 32 n-tiles

    const __half* gA = g_xh + (size_t)tile_m * TM * IN_F;
    const __half* gB = g_wt + (size_t)tile_n * TN * IN_F;

    const uint32_t a_row  = (uint32_t)(wm * 64 + (lane & 15));
    const uint32_t a_colb = (uint32_t)((lane >> 4) << 4);
    const uint32_t b_row  = (uint32_t)(wn * 64 + ((lane >> 4) << 3) + (lane & 7));
    const uint32_t b_colb = (uint32_t)(((lane >> 3) & 1) << 4);

    float acc[4][8][4];
    #pragma unroll
    for (int t = 0; t < 4; t++)
        #pragma unroll
        for (int j = 0; j < 8; j++)
            #pragma unroll
            for (int q = 0; q < 4; q++) acc[t][j][q] = 0.0f;

    // Prologue: fill stages 0,1
    #pragma unroll
    for (int p = 0; p < STAGES - 1; p++) {
        load_stage(S0 + (uint32_t)p * STAGE, tid, gA, gB, p);
        asm volatile("cp.async.commit_group;" ::: "memory");
    }

    uint32_t af[2][4][4], bf[2][4][4];

    for (int it = 0; it < NK; ++it) {
        asm volatile("cp.async.wait_group %0;" :: "n"(STAGES - 2) : "memory");
        __syncthreads();

        const uint32_t stA = S0 + (uint32_t)(it % STAGES) * STAGE;
        const uint32_t stB = stA + A_ST;

        const int j = it + (STAGES - 1);
        const bool doload = (j < NK);
        const uint32_t stJ = S0 + (uint32_t)(j % STAGES) * STAGE;
        const __half* nA = gA + (size_t)j * KS;
        const __half* nB = gB + (size_t)j * KS;

        // preload kk=0 fragments (exposure covered by co-resident CTA)
        #pragma unroll
        for (int t = 0; t < 4; t++) {
            uint32_t off = (a_row + t * 16u) * 128u + a_colb;
            ldsm4(af[0][t][0], af[0][t][1], af[0][t][2], af[0][t][3], stA + sw128(off));
        }
        #pragma unroll
        for (int p = 0; p < 4; p++) {
            uint32_t off = (b_row + p * 16u) * 128u + b_colb;
            ldsm4(bf[0][p][0], bf[0][p][1], bf[0][p][2], bf[0][p][3], stB + sw128(off));
        }

        #pragma unroll
        for (int kk = 0; kk < 4; kk++) {
            const int cur = kk & 1;
            const int nxt = cur ^ 1;
            // prefetch fragments for kk+1 (overlaps with MMAs below)
            if (kk < 3) {
                const uint32_t kc = (uint32_t)((kk + 1) * 32);
                #pragma unroll
                for (int t = 0; t < 4; t++) {
                    uint32_t off = (a_row + t * 16u) * 128u + kc + a_colb;
                    ldsm4(af[nxt][t][0], af[nxt][t][1], af[nxt][t][2], af[nxt][t][3],
                          stA + sw128(off));
                }
                #pragma unroll
                for (int p = 0; p < 4; p++) {
                    uint32_t off = (b_row + p * 16u) * 128u + kc + b_colb;
                    ldsm4(bf[nxt][p][0], bf[nxt][p][1], bf[nxt][p][2], bf[nxt][p][3],
                          stB + sw128(off));
                }
            }
            // spread next-stage global loads: 4 chunks per kk (16 total)
            if (doload) {
                #pragma unroll
                for (int c = 0; c < 4; c++) load_chunk(stJ, tid, nA, nB, kk * 4 + c);
            }
            // 32 MMAs on current fragments
            #pragma unroll
            for (int t = 0; t < 4; t++) {
                #pragma unroll
                for (int p = 0; p < 4; p++) {
                    mma16816(acc[t][2*p][0], acc[t][2*p][1], acc[t][2*p][2], acc[t][2*p][3],
                             af[cur][t][0], af[cur][t][1], af[cur][t][2], af[cur][t][3],
                             bf[cur][p][0], bf[cur][p][1]);
                    mma16816(acc[t][2*p+1][0], acc[t][2*p+1][1], acc[t][2*p+1][2], acc[t][2*p+1][3],
                             af[cur][t][0], af[cur][t][1], af[cur][t][2], af[cur][t][3],
                             bf[cur][p][2], bf[cur][p][3]);
                }
            }
        }
        asm volatile("cp.async.commit_group;" ::: "memory");
        // No trailing barrier: next iteration's wait+barrier fences stage reuse.
    }

    // Epilogue: acc + bias -> gmem fp32
    const int n_base = tile_n * TN + wn * 64 + (lane & 3) * 2;
    float2 bv[8];
    #pragma unroll
    for (int jj = 0; jj < 8; jj++)
        bv[jj] = *(const float2*)(bias + n_base + jj * 8);

    const int m_base = tile_m * TM + wm * 64 + (lane >> 2);
    #pragma unroll
    for (int t = 0; t < 4; t++) {
        float* r0 = out + (size_t)(m_base + t * 16) * OUT_F + n_base;
        float* r1 = r0 + 8 * OUT_F;
        #pragma unroll
        for (int jj = 0; jj < 8; jj++) {
            float2 v0 = make_float2(acc[t][jj][0] + bv[jj].x, acc[t][jj][1] + bv[jj].y);
            float2 v1 = make_float2(acc[t][jj][2] + bv[jj].x, acc[t][jj][3] + bv[jj].y);
            *(float2*)(r0 + jj * 8) = v0;
            *(float2*)(r1 + jj * 8) = v1;
        }
    }
}

// ----------------------------------------------------------------------------
extern "C" void kernel_launch(void* const* d_in, const int* in_sizes, int n_in,
                              void* d_out, int out_size) {
    (void)in_sizes; (void)n_in; (void)out_size;
    const float* x = (const float*)d_in[0];
    const float* w = (const float*)d_in[1];
    const float* b = (const float*)d_in[2];
    float* out = (float*)d_out;

    cvt_fused_kernel<<<W_BLOCKS + X_BLOCKS, 256>>>(x, w);

    cudaFuncSetAttribute(gemm_hmma_kernel, cudaFuncAttributeMaxDynamicSharedMemorySize,
                         (int)SMEM_BYTES);
    gemm_hmma_kernel<<<(BATCH / TM) * (OUT_F / TN), 128, SMEM_BYTES>>>(b, out);
}

// round 8
// speedup vs baseline: 1.2251x; 1.1447x over previous
#include <cuda_runtime.h>
#include <cuda_fp16.h>
#include <cstdint>

// ============================================================================
// out[8192,4096] = x[8192,4096] @ W[4096(k),4096(n)] + b
// sm_103 base-ISA: cp.async 4-stage + ldmatrix + mma.sync.m16n8k16 (fp32 acc)
// R8: GEMM identical to R5 (best: 577us, tensor 78.2%).
//     cvt: W transpose re-tiled to 64x64 for full 128B store transactions.
// ============================================================================

static constexpr int BATCH = 8192;
static constexpr int IN_F  = 4096;   // K
static constexpr int OUT_F = 4096;   // N

static constexpr int TM = 128;
static constexpr int TN = 256;
static constexpr int KS = 64;              // K per stage (128B rows)
static constexpr int NK = IN_F / KS;       // 64
static constexpr int STAGES = 4;

static constexpr uint32_t A_ST = TM * 128u;                 // 16 KB
static constexpr uint32_t B_ST = TN * 128u;                 // 32 KB
static constexpr uint32_t STAGE = A_ST + B_ST;              // 48 KB
static constexpr uint32_t SMEM_BYTES = 1024u + STAGES * STAGE;

__device__ __align__(128) __half g_xh[(size_t)BATCH * IN_F];  // x fp16 [M,K]
__device__ __align__(128) __half g_wt[(size_t)OUT_F * IN_F];  // W^T fp16 [N,K]

// ----------------------------------------------------------------------------
__device__ __forceinline__ uint32_t smem_u32(const void* p) {
    uint32_t a;
    asm("{ .reg .u64 t; cvta.to.shared.u64 t, %1; cvt.u32.u64 %0, t; }" : "=r"(a) : "l"(p));
    return a;
}
__device__ __forceinline__ uint32_t sw128(uint32_t off) {
    return off ^ ((off >> 3) & 0x70u);
}
__device__ __forceinline__ void cp16(uint32_t s, const void* g) {
    asm volatile("cp.async.cg.shared.global [%0], [%1], 16;" :: "r"(s), "l"(g));
}
__device__ __forceinline__ void ldsm4(uint32_t& r0, uint32_t& r1, uint32_t& r2, uint32_t& r3,
                                      uint32_t addr) {
    asm volatile("ldmatrix.sync.aligned.m8n8.x4.shared.b16 {%0,%1,%2,%3}, [%4];"
                 : "=r"(r0), "=r"(r1), "=r"(r2), "=r"(r3) : "r"(addr));
}
__device__ __forceinline__ void mma16816(float& c0, float& c1, float& c2, float& c3,
                                         uint32_t a0, uint32_t a1, uint32_t a2, uint32_t a3,
                                         uint32_t b0, uint32_t b1) {
    asm volatile(
        "mma.sync.aligned.m16n8k16.row.col.f32.f16.f16.f32 "
        "{%0,%1,%2,%3}, {%4,%5,%6,%7}, {%8,%9}, {%0,%1,%2,%3};"
        : "+f"(c0), "+f"(c1), "+f"(c2), "+f"(c3)
        : "r"(a0), "r"(a1), "r"(a2), "r"(a3), "r"(b0), "r"(b1));
}

// ----------------------------------------------------------------------------
// Fused preprocessing.
// W blocks: 64x64 transpose tiles -> 256B reads of w, 128B writes of g_wt.
// X blocks: fp32 -> fp16 streaming convert.
// ----------------------------------------------------------------------------
static constexpr int W_BLOCKS = (OUT_F / 64) * (IN_F / 64);   // 4096
static constexpr int X_BLOCKS = 4096;

__global__ void __launch_bounds__(256)
cvt_fused_kernel(const float* __restrict__ x, const float* __restrict__ w) {
    const int bid = blockIdx.x;
    if (bid < W_BLOCKS) {
        // Transpose-convert one 64(i) x 64(o) block of W into g_wt[o][i].
        __shared__ __half tile[64][66];   // pad 66: column reads conflict-free
        const int bx = bid & ((OUT_F / 64) - 1);   // o block
        const int by = bid >> 6;                   // i block (IN_F/64 = 64)
        const int i0 = by * 64;
        const int o0 = bx * 64;
        const int tc = threadIdx.x & 63;   // 0..63
        const int tr = threadIdx.x >> 6;   // 0..3
        #pragma unroll
        for (int r = 0; r < 16; r++) {
            const int i = tr + r * 4;      // 0..63
            tile[i][tc] = __float2half(w[(size_t)(i0 + i) * OUT_F + o0 + tc]);
        }
        __syncthreads();
        #pragma unroll
        for (int r = 0; r < 16; r++) {
            const int o = tr + r * 4;      // 0..63
            g_wt[(size_t)(o0 + o) * IN_F + i0 + tc] = tile[tc][o];
        }
    } else {
        const size_t n8 = (size_t)BATCH * IN_F / 8;
        const size_t stride = (size_t)X_BLOCKS * 256;
        for (size_t i = (size_t)(bid - W_BLOCKS) * 256 + threadIdx.x; i < n8; i += stride) {
            float4 a = ((const float4*)x)[2 * i];
            float4 c = ((const float4*)x)[2 * i + 1];
            __half2 h0 = __floats2half2_rn(a.x, a.y);
            __half2 h1 = __floats2half2_rn(a.z, a.w);
            __half2 h2 = __floats2half2_rn(c.x, c.y);
            __half2 h3 = __floats2half2_rn(c.z, c.w);
            uint4 o;
            o.x = *reinterpret_cast<uint32_t*>(&h0);
            o.y = *reinterpret_cast<uint32_t*>(&h1);
            o.z = *reinterpret_cast<uint32_t*>(&h2);
            o.w = *reinterpret_cast<uint32_t*>(&h3);
            ((uint4*)g_xh)[i] = o;
        }
    }
}

// ----------------------------------------------------------------------------
// GEMM: 128x256 tile / CTA, 256 threads (8 warps, 2M x 4N, warp tile 64x64)
// Identical to R5.
// ----------------------------------------------------------------------------
__device__ __forceinline__ void load_chunk(uint32_t st, int tid,
                                           const __half* a, const __half* b, int q) {
    if (q < 4) {
        int id = tid + (q << 8);
        int row = id >> 3;
        int c = id & 7;
        uint32_t sw = sw128(((uint32_t)row << 7) | ((uint32_t)c << 4));
        cp16(st + sw, a + (size_t)row * IN_F + (c << 3));
    } else {
        int id = tid + ((q - 4) << 8);
        int row = id >> 3;
        int c = id & 7;
        uint32_t sw = sw128(((uint32_t)row << 7) | ((uint32_t)c << 4));
        cp16(st + A_ST + sw, b + (size_t)row * IN_F + (c << 3));
    }
}

__device__ __forceinline__ void load_stage(uint32_t st, int tid,
                                           const __half* gA, const __half* gB, int kslab) {
    const __half* a = gA + (size_t)kslab * KS;
    const __half* b = gB + (size_t)kslab * KS;
    #pragma unroll
    for (int q = 0; q < 12; q++) load_chunk(st, tid, a, b, q);
}

__global__ void __launch_bounds__(256, 1)
gemm_hmma_kernel(const float* __restrict__ bias, float* __restrict__ out) {
    extern __shared__ char smem_raw[];
    const uint32_t S0 = (smem_u32(smem_raw) + 1023u) & ~1023u;

    const int tid  = threadIdx.x;
    const int wid  = tid >> 5;
    const int lane = tid & 31;
    const int wm   = wid & 1;
    const int wn   = wid >> 1;
    const int tile_m = blockIdx.x >> 4;
    const int tile_n = blockIdx.x & 15;

    const __half* gA = g_xh + (size_t)tile_m * TM * IN_F;
    const __half* gB = g_wt + (size_t)tile_n * TN * IN_F;

    const uint32_t a_row  = (uint32_t)(wm * 64 + (lane & 15));
    const uint32_t a_colb = (uint32_t)((lane >> 4) << 4);
    const uint32_t b_row  = (uint32_t)(wn * 64 + ((lane >> 4) << 3) + (lane & 7));
    const uint32_t b_colb = (uint32_t)(((lane >> 3) & 1) << 4);

    float acc[4][8][4];
    #pragma unroll
    for (int t = 0; t < 4; t++)
        #pragma unroll
        for (int j = 0; j < 8; j++)
            #pragma unroll
            for (int q = 0; q < 4; q++) acc[t][j][q] = 0.0f;

    // Prologue: fill stages 0..2
    #pragma unroll
    for (int p = 0; p < STAGES - 1; p++) {
        load_stage(S0 + (uint32_t)p * STAGE, tid, gA, gB, p);
        asm volatile("cp.async.commit_group;" ::: "memory");
    }
    asm volatile("cp.async.wait_group 1;" ::: "memory");   // stages 0,1 complete
    __syncthreads();

    uint32_t af[2][4][4], bf[2][4][4];

    // Preload iteration 0 / kk=0 fragments into buffer 0
    #pragma unroll
    for (int t = 0; t < 4; t++) {
        uint32_t off = (a_row + t * 16u) * 128u + a_colb;
        ldsm4(af[0][t][0], af[0][t][1], af[0][t][2], af[0][t][3], S0 + sw128(off));
    }
    #pragma unroll
    for (int p = 0; p < 4; p++) {
        uint32_t off = (b_row + p * 16u) * 128u + b_colb;
        ldsm4(bf[0][p][0], bf[0][p][1], bf[0][p][2], bf[0][p][3], S0 + A_ST + sw128(off));
    }

    for (int it = 0; it < NK; ++it) {
        const uint32_t stA = S0 + (uint32_t)(it % STAGES) * STAGE;
        const uint32_t stB = stA + A_ST;
        const uint32_t stNext = S0 + (uint32_t)((it + 1) % STAGES) * STAGE;
        const bool last = (it == NK - 1);

        const int j = it + (STAGES - 1);
        const bool doload = (j < NK);
        const uint32_t stJ = S0 + (uint32_t)(j % STAGES) * STAGE;
        const __half* nA = gA + (size_t)j * KS;
        const __half* nB = gB + (size_t)j * KS;

        #pragma unroll
        for (int kk = 0; kk < 4; kk++) {
            const int cur = kk & 1;
            const int nxt = cur ^ 1;
            // prefetch fragments: kk+1 of this stage, or kk=0 of the NEXT stage at kk=3
            if (kk < 3) {
                const uint32_t kc = (uint32_t)((kk + 1) * 32);
                #pragma unroll
                for (int t = 0; t < 4; t++) {
                    uint32_t off = (a_row + t * 16u) * 128u + kc + a_colb;
                    ldsm4(af[nxt][t][0], af[nxt][t][1], af[nxt][t][2], af[nxt][t][3],
                          stA + sw128(off));
                }
                #pragma unroll
                for (int p = 0; p < 4; p++) {
                    uint32_t off = (b_row + p * 16u) * 128u + kc + b_colb;
                    ldsm4(bf[nxt][p][0], bf[nxt][p][1], bf[nxt][p][2], bf[nxt][p][3],
                          stB + sw128(off));
                }
            } else if (!last) {
                #pragma unroll
                for (int t = 0; t < 4; t++) {
                    uint32_t off = (a_row + t * 16u) * 128u + a_colb;
                    ldsm4(af[nxt][t][0], af[nxt][t][1], af[nxt][t][2], af[nxt][t][3],
                          stNext + sw128(off));
                }
                #pragma unroll
                for (int p = 0; p < 4; p++) {
                    uint32_t off = (b_row + p * 16u) * 128u + b_colb;
                    ldsm4(bf[nxt][p][0], bf[nxt][p][1], bf[nxt][p][2], bf[nxt][p][3],
                          stNext + A_ST + sw128(off));
                }
            }
            // spread next-stage global loads: 3 chunks per kk
            if (doload) {
                #pragma unroll
                for (int c = 0; c < 3; c++) load_chunk(stJ, tid, nA, nB, kk * 3 + c);
            }
            // 32 MMAs on current fragments
            #pragma unroll
            for (int t = 0; t < 4; t++) {
                #pragma unroll
                for (int p = 0; p < 4; p++) {
                    mma16816(acc[t][2*p][0], acc[t][2*p][1], acc[t][2*p][2], acc[t][2*p][3],
                             af[cur][t][0], af[cur][t][1], af[cur][t][2], af[cur][t][3],
                             bf[cur][p][0], bf[cur][p][1]);
                    mma16816(acc[t][2*p+1][0], acc[t][2*p+1][1], acc[t][2*p+1][2], acc[t][2*p+1][3],
                             af[cur][t][0], af[cur][t][1], af[cur][t][2], af[cur][t][3],
                             bf[cur][p][2], bf[cur][p][3]);
                }
            }
        }
        asm volatile("cp.async.commit_group;" ::: "memory");
        if (!last) {
            asm volatile("cp.async.wait_group 1;" ::: "memory");
            __syncthreads();
        }
    }

    // Epilogue: acc + bias -> gmem fp32
    const int n_base = tile_n * TN + wn * 64 + (lane & 3) * 2;
    float2 bv[8];
    #pragma unroll
    for (int jj = 0; jj < 8; jj++)
        bv[jj] = *(const float2*)(bias + n_base + jj * 8);

    const int m_base = tile_m * TM + wm * 64 + (lane >> 2);
    #pragma unroll
    for (int t = 0; t < 4; t++) {
        float* r0 = out + (size_t)(m_base + t * 16) * OUT_F + n_base;
        float* r1 = r0 + 8 * OUT_F;
        #pragma unroll
        for (int jj = 0; jj < 8; jj++) {
            float2 v0 = make_float2(acc[t][jj][0] + bv[jj].x, acc[t][jj][1] + bv[jj].y);
            float2 v1 = make_float2(acc[t][jj][2] + bv[jj].x, acc[t][jj][3] + bv[jj].y);
            *(float2*)(r0 + jj * 8) = v0;
            *(float2*)(r1 + jj * 8) = v1;
        }
    }
}

// ----------------------------------------------------------------------------
extern "C" void kernel_launch(void* const* d_in, const int* in_sizes, int n_in,
                              void* d_out, int out_size) {
    (void)in_sizes; (void)n_in; (void)out_size;
    const float* x = (const float*)d_in[0];
    const float* w = (const float*)d_in[1];
    const float* b = (const float*)d_in[2];
    float* out = (float*)d_out;

    cvt_fused_kernel<<<W_BLOCKS + X_BLOCKS, 256>>>(x, w);

    cudaFuncSetAttribute(gemm_hmma_kernel, cudaFuncAttributeMaxDynamicSharedMemorySize,
                         (int)SMEM_BYTES);
    gemm_hmma_kernel<<<(BATCH / TM) * (OUT_F / TN), 256, SMEM_BYTES>>>(b, out);
}